// round 1
// baseline (speedup 1.0000x reference)
#include <cuda_runtime.h>
#include <stdint.h>

#define N_SEG 128
#define S_VID 2048
#define HDIM  256
#define DDIM  512
#define RTOT  (N_SEG + S_VID)   // 2176
#define NEGV  (-1000.0f)

// -------- device scratch (no allocations allowed) --------
__device__ float g_P[RTOT * HDIM];          // rows 0..127: A(+b1), rows 128..: B
__device__ float g_logitsT[S_VID * N_SEG];  // [s][n]
__device__ float g_logsigT[S_VID * N_SEG];  // [s][n]

// ============================================================
// K1: P[r][h] = dot(x_r, W1_row_h_half) (+ b1[h] for seg rows)
//   r<128: seg row r, W1[h][0:512];  r>=128: vid row r-128, W1[h][512:1024]
//   BM=64 rows x BN=64 h, BK=32, 256 threads, 4x4 microtile
// ============================================================
__global__ __launch_bounds__(256) void gemm_k1(
    const float* __restrict__ seg, const float* __restrict__ vid,
    const float* __restrict__ W1, const float* __restrict__ b1)
{
    __shared__ float Xs[64][33];
    __shared__ float Ws[64][33];
    const int r0 = blockIdx.x * 64;
    const int h0 = blockIdx.y * 64;
    const int t  = threadIdx.x;
    const int tm = (t >> 4) * 4;  // row in tile
    const int tn = (t & 15) * 4;  // h in tile
    const int koff = (r0 < N_SEG) ? 0 : DDIM;

    float acc[4][4];
    #pragma unroll
    for (int i = 0; i < 4; i++)
        #pragma unroll
        for (int j = 0; j < 4; j++) acc[i][j] = 0.0f;

    for (int k0 = 0; k0 < DDIM; k0 += 32) {
        #pragma unroll
        for (int i = 0; i < 8; i++) {
            int idx = t + i * 256;
            int rr = idx >> 5, kk = idx & 31;
            int r = r0 + rr;
            const float* src = (r < N_SEG) ? (seg + (size_t)r * DDIM)
                                           : (vid + (size_t)(r - N_SEG) * DDIM);
            Xs[rr][kk] = src[k0 + kk];
        }
        #pragma unroll
        for (int i = 0; i < 8; i++) {
            int idx = t + i * 256;
            int hh = idx >> 5, kk = idx & 31;
            Ws[hh][kk] = W1[(size_t)(h0 + hh) * (2 * DDIM) + koff + k0 + kk];
        }
        __syncthreads();
        #pragma unroll
        for (int k = 0; k < 32; k++) {
            float a[4], w[4];
            #pragma unroll
            for (int i = 0; i < 4; i++) a[i] = Xs[tm + i][k];
            #pragma unroll
            for (int j = 0; j < 4; j++) w[j] = Ws[tn + j][k];
            #pragma unroll
            for (int i = 0; i < 4; i++)
                #pragma unroll
                for (int j = 0; j < 4; j++) acc[i][j] += a[i] * w[j];
        }
        __syncthreads();
    }
    #pragma unroll
    for (int i = 0; i < 4; i++) {
        int r = r0 + tm + i;
        #pragma unroll
        for (int j = 0; j < 4; j++) {
            int h = h0 + tn + j;
            float v = acc[i][j];
            if (r < N_SEG) v += b1[h];
            g_P[(size_t)r * HDIM + h] = v;
        }
    }
}

// ============================================================
// K2: logitsT[s][n] = sum_h relu(A'[n][h] + B[s][h]) * W2[h] + b2
//     also logsigT = log_sigmoid(logits)
//   BM=32 n x BN=64 s, BK=32 h, 256 threads, 2x4 microtile
// ============================================================
__global__ __launch_bounds__(256) void fused_k2(
    const float* __restrict__ W2, const float* __restrict__ b2)
{
    __shared__ float As[32][33];
    __shared__ float Bs[64][33];
    __shared__ float w2s[32];
    const int n0 = blockIdx.x * 32;
    const int s0 = blockIdx.y * 64;
    const int t  = threadIdx.x;
    const int tn = (t >> 4) * 2;  // n pair
    const int ts = (t & 15) * 4;  // s quad
    const float bb2 = b2[0];

    float acc[2][4];
    #pragma unroll
    for (int i = 0; i < 2; i++)
        #pragma unroll
        for (int j = 0; j < 4; j++) acc[i][j] = 0.0f;

    for (int k0 = 0; k0 < HDIM; k0 += 32) {
        #pragma unroll
        for (int i = 0; i < 4; i++) {
            int idx = t + i * 256;
            int rr = idx >> 5, kk = idx & 31;
            As[rr][kk] = g_P[(size_t)(n0 + rr) * HDIM + k0 + kk];
        }
        #pragma unroll
        for (int i = 0; i < 8; i++) {
            int idx = t + i * 256;
            int rr = idx >> 5, kk = idx & 31;
            Bs[rr][kk] = g_P[(size_t)(N_SEG + s0 + rr) * HDIM + k0 + kk];
        }
        if (t < 32) w2s[t] = W2[k0 + t];
        __syncthreads();
        #pragma unroll
        for (int k = 0; k < 32; k++) {
            float w = w2s[k];
            float a0 = As[tn][k], a1 = As[tn + 1][k];
            #pragma unroll
            for (int j = 0; j < 4; j++) {
                float bj = Bs[ts + j][k];
                acc[0][j] += fmaxf(a0 + bj, 0.0f) * w;
                acc[1][j] += fmaxf(a1 + bj, 0.0f) * w;
            }
        }
        __syncthreads();
    }
    #pragma unroll
    for (int i = 0; i < 2; i++) {
        int n = n0 + tn + i;
        #pragma unroll
        for (int j = 0; j < 4; j++) {
            int s = s0 + ts + j;
            float L = acc[i][j] + bb2;
            g_logitsT[(size_t)s * N_SEG + n] = L;
            // stable log_sigmoid: min(0,x) - log1p(exp(-|x|))
            float ls = fminf(L, 0.0f) - log1pf(expf(-fabsf(L)));
            g_logsigT[(size_t)s * N_SEG + n] = ls;
        }
    }
}

// ============================================================
// K3: serial DP (warp 0) + chunk prefetch (warps 1..3) + walk + outputs
// ============================================================
template<bool CLAMP>
__device__ __forceinline__ void dp_chunk(const float* __restrict__ buf, int c, int L,
                                         float& p0, float& p1, float& p2, float& p3,
                                         unsigned* __restrict__ rowbits)
{
    unsigned a0 = 0, a1 = 0, a2 = 0, a3 = 0;
    const int n0 = 4 * L;
    #pragma unroll 8
    for (int i = 31; i >= 0; i--) {
        float4 ls = *(const float4*)(buf + i * 128 + n0);
        float nxt3 = __shfl_down_sync(0xffffffffu, p0, 1);
        if (L == 31) nxt3 = 0.0f;               // n=127: adds 0
        float c0 = ls.x + p1;
        float c1 = ls.y + p2;
        float c2 = ls.z + p3;
        float c3 = ls.w + nxt3;
        a0 = a0 + a0 + (unsigned)(c0 >= p0);
        a1 = a1 + a1 + (unsigned)(c1 >= p1);
        a2 = a2 + a2 + (unsigned)(c2 >= p2);
        a3 = a3 + a3 + (unsigned)(c3 >= p3);
        float v0 = fmaxf(c0, p0);
        float v1 = fmaxf(c1, p1);
        float v2 = fmaxf(c2, p2);
        float v3 = fmaxf(c3, p3);
        if (CLAMP) {
            int s = c * 32 + i;
            v0 = (s >= n0     && s <= 1920 + n0) ? v0 : NEGV;
            v1 = (s >= n0 + 1 && s <= 1921 + n0) ? v1 : NEGV;
            v2 = (s >= n0 + 2 && s <= 1922 + n0) ? v2 : NEGV;
            v3 = (s >= n0 + 3 && s <= 1923 + n0) ? v3 : NEGV;
        }
        p0 = v0; p1 = v1; p2 = v2; p3 = v3;
    }
    *(uint4*)(rowbits + c * 128 + n0) = make_uint4(a0, a1, a2, a3);
}

__global__ __launch_bounds__(128) void dp_k3(float* __restrict__ out, int out_size)
{
    extern __shared__ unsigned char smraw[];
    float*    lsbuf    = (float*)smraw;                    // [2][32][128]
    unsigned* rowbits  = (unsigned*)(lsbuf + 2 * 32 * 128); // [64][128] (word c, row n)
    int*      alignArr = (int*)(rowbits + 64 * 128);        // [128]
    float*    redbuf   = (float*)(alignArr + 128);          // [4]

    const int t = threadIdx.x;
    const int L = t & 31;
    alignArr[t] = 0;

    // preload chunk 63 (buffer 1)
    if (t >= 32) {
        int lt = t - 32;
        const float4* src = (const float4*)(g_logsigT + 63 * 4096);
        float4* dst = (float4*)(lsbuf + (63 & 1) * 4096);
        for (int i = lt; i < 1024; i += 96) dst[i] = src[i];
    }
    __syncthreads();

    float p0 = NEGV, p1 = NEGV, p2 = NEGV, p3 = NEGV;
    for (int c = 63; c >= 0; c--) {
        if (t >= 32) {
            if (c > 0) {
                int lt = t - 32;
                const float4* src = (const float4*)(g_logsigT + (size_t)(c - 1) * 4096);
                float4* dst = (float4*)(lsbuf + ((c - 1) & 1) * 4096);
                for (int i = lt; i < 1024; i += 96) dst[i] = src[i];
            }
        } else {
            const float* buf = lsbuf + (c & 1) * 4096;
            if (c >= 4 && c <= 59) dp_chunk<false>(buf, c, L, p0, p1, p2, p3, rowbits);
            else                   dp_chunk<true >(buf, c, L, p0, p1, p2, p3, rowbits);
        }
        __syncthreads();
    }

    // walk: for each n, first set take-bit at s >= scur (equivalent to ref scan)
    if (t == 0) {
        int scur = 0;
        for (int n = 0; n < 128; n++) {
            int w = scur >> 5;
            unsigned word = rowbits[w * 128 + n] & (0xFFFFFFFFu << (scur & 31));
            while (word == 0) {
                w++;
                if (w >= 64) break;
                word = rowbits[w * 128 + n];
            }
            if (w >= 64) break;        // n stuck forever -> remaining aligns = 0
            int s = w * 32 + (__ffs(word) - 1);
            alignArr[n] = s;
            scur = s + 1;
            if (scur >= S_VID) break;  // s exhausted -> remaining aligns = 0
        }
    }
    __syncthreads();

    // outputs: adjacency ones + aggregated mean
    int a = alignArr[t];
    out[(size_t)(S_VID + t) * RTOT + a] = 1.0f;
    float v = g_logitsT[(size_t)a * N_SEG + t];
    #pragma unroll
    for (int o = 16; o; o >>= 1) v += __shfl_down_sync(0xffffffffu, v, o);
    if (L == 0) redbuf[t >> 5] = v;
    __syncthreads();
    if (t == 0) {
        float sum = redbuf[0] + redbuf[1] + redbuf[2] + redbuf[3];
        if (out_size > RTOT * RTOT) out[(size_t)RTOT * RTOT] = sum * (1.0f / 128.0f);
    }
}

// ============================================================
extern "C" void kernel_launch(void* const* d_in, const int* in_sizes, int n_in,
                              void* d_out, int out_size)
{
    const float* seg = (const float*)d_in[0];
    const float* vid = (const float*)d_in[1];
    const float* W1  = (const float*)d_in[2];
    const float* b1  = (const float*)d_in[3];
    const float* W2  = (const float*)d_in[4];
    const float* b2  = (const float*)d_in[5];
    float* out = (float*)d_out;

    cudaMemsetAsync(out, 0, (size_t)out_size * sizeof(float), 0);
    gemm_k1<<<dim3(34, 4), 256>>>(seg, vid, W1, b1);
    fused_k2<<<dim3(4, 32), 256>>>(W2, b2);

    const int smem_k3 = (2 * 32 * 128) * 4 + (64 * 128) * 4 + 128 * 4 + 4 * 4;
    cudaFuncSetAttribute(dp_k3, cudaFuncAttributeMaxDynamicSharedMemorySize, smem_k3);
    dp_k3<<<1, 128, smem_k3>>>(out, out_size);
}

// round 2
// speedup vs baseline: 1.0363x; 1.0363x over previous
#include <cuda_runtime.h>
#include <stdint.h>

#define N_SEG 128
#define S_VID 2048
#define HDIM  256
#define DDIM  512
#define RTOT  (N_SEG + S_VID)   // 2176
#define NEGV  (-1000.0f)

// -------- device scratch (no allocations allowed) --------
__device__ float g_P[RTOT * HDIM];          // rows 0..127: A(+b1), rows 128..: B
__device__ float g_logitsT[S_VID * N_SEG];  // [s][n]
__device__ float g_logsigT[S_VID * N_SEG];  // [s][n]

typedef unsigned long long u64;

__device__ __forceinline__ u64 dup2(float a) {
    u64 d; asm("mov.b64 %0,{%1,%1};" : "=l"(d) : "f"(a)); return d;
}
__device__ __forceinline__ u64 pack2(float lo, float hi) {
    u64 d; asm("mov.b64 %0,{%1,%2};" : "=l"(d) : "f"(lo), "f"(hi)); return d;
}
__device__ __forceinline__ void unpack2(u64 v, float& lo, float& hi) {
    asm("mov.b64 {%0,%1},%2;" : "=f"(lo), "=f"(hi) : "l"(v));
}
__device__ __forceinline__ void fma2(u64& acc, u64 a, u64 b) {
    asm("fma.rn.f32x2 %0,%1,%2,%0;" : "+l"(acc) : "l"(a), "l"(b));
}
__device__ __forceinline__ u64 add2v(u64 a, u64 b) {
    u64 c; asm("add.rn.f32x2 %0,%1,%2;" : "=l"(c) : "l"(a), "l"(b)); return c;
}

// ============================================================
// K1: P[r][h] = dot(x_r, W1_half_row_h) (+ b1[h] for seg rows)
//   64 rows x 64 h tile, BK=32, 256 threads, 4x4 microtile, f32x2 FMA
//   k-major smem, XOR-swizzled (conflict-free STS, aligned LDS.128)
// ============================================================
__global__ __launch_bounds__(256) void gemm_k1(
    const float* __restrict__ seg, const float* __restrict__ vid,
    const float* __restrict__ W1, const float* __restrict__ b1)
{
    __shared__ float Xs[32][68];
    __shared__ float Ws[32][68];
    const int r0 = blockIdx.x * 64;
    const int h0 = blockIdx.y * 64;
    const int t  = threadIdx.x;
    const int tm = (t >> 4) * 4;
    const int tn = (t & 15) * 4;
    const int koff = (r0 < N_SEG) ? 0 : DDIM;
    const float* xbase = (r0 < N_SEG) ? (seg + (size_t)r0 * DDIM)
                                      : (vid + (size_t)(r0 - N_SEG) * DDIM);

    u64 acc[4][2];
    #pragma unroll
    for (int i = 0; i < 4; i++) { acc[i][0] = 0ull; acc[i][1] = 0ull; }

    float4 xreg[2], wreg[2];
    // preload k0 = 0 (coalesced: 8 consecutive lanes cover one row's 32 floats)
    #pragma unroll
    for (int p = 0; p < 2; p++) {
        int idx = t + p * 256;
        int rr = idx >> 3, fq = idx & 7;
        xreg[p] = *(const float4*)(xbase + (size_t)rr * DDIM + 4 * fq);
        wreg[p] = *(const float4*)(W1 + (size_t)(h0 + rr) * (2 * DDIM) + koff + 4 * fq);
    }

    for (int k0 = 0; k0 < DDIM; k0 += 32) {
        __syncthreads();
        #pragma unroll
        for (int p = 0; p < 2; p++) {
            int idx = t + p * 256;
            int rr = idx >> 3, fq = idx & 7;
            int col = rr ^ (4 * fq);
            Xs[4 * fq + 0][col] = xreg[p].x;
            Xs[4 * fq + 1][col] = xreg[p].y;
            Xs[4 * fq + 2][col] = xreg[p].z;
            Xs[4 * fq + 3][col] = xreg[p].w;
            Ws[4 * fq + 0][col] = wreg[p].x;
            Ws[4 * fq + 1][col] = wreg[p].y;
            Ws[4 * fq + 2][col] = wreg[p].z;
            Ws[4 * fq + 3][col] = wreg[p].w;
        }
        __syncthreads();
        if (k0 + 32 < DDIM) {
            #pragma unroll
            for (int p = 0; p < 2; p++) {
                int idx = t + p * 256;
                int rr = idx >> 3, fq = idx & 7;
                xreg[p] = *(const float4*)(xbase + (size_t)rr * DDIM + k0 + 32 + 4 * fq);
                wreg[p] = *(const float4*)(W1 + (size_t)(h0 + rr) * (2 * DDIM) + koff + k0 + 32 + 4 * fq);
            }
        }
        #pragma unroll
        for (int kk = 0; kk < 32; kk++) {
            int q4 = 4 * (kk >> 2);
            float4 av = *(const float4*)&Xs[kk][tm ^ q4];
            ulonglong2 wv = *(const ulonglong2*)&Ws[kk][tn ^ q4];
            u64 ad;
            ad = dup2(av.x); fma2(acc[0][0], ad, wv.x); fma2(acc[0][1], ad, wv.y);
            ad = dup2(av.y); fma2(acc[1][0], ad, wv.x); fma2(acc[1][1], ad, wv.y);
            ad = dup2(av.z); fma2(acc[2][0], ad, wv.x); fma2(acc[2][1], ad, wv.y);
            ad = dup2(av.w); fma2(acc[3][0], ad, wv.x); fma2(acc[3][1], ad, wv.y);
        }
    }

    #pragma unroll
    for (int i = 0; i < 4; i++) {
        int r = r0 + tm + i;
        #pragma unroll
        for (int jp = 0; jp < 2; jp++) {
            float v0, v1;
            unpack2(acc[i][jp], v0, v1);
            int h = tn + 2 * jp;
            if (r0 < N_SEG) { v0 += b1[h0 + h]; v1 += b1[h0 + h + 1]; }
            g_P[(size_t)r * HDIM + h0 + h]     = v0;
            g_P[(size_t)r * HDIM + h0 + h + 1] = v1;
        }
    }
}

// ============================================================
// K2: logitsT[s][n] = sum_h relu(A'[n][h] + B[s][h]) * W2[h] + b2
//     logsigT = log_sigmoid(logits)
//   32 n x 64 s tile, BK=32 h, 256 threads, 2x4 microtile, packed over s
// ============================================================
__global__ __launch_bounds__(256) void fused_k2(
    const float* __restrict__ W2, const float* __restrict__ b2)
{
    __shared__ float As[32][36];
    __shared__ float Bs[32][68];
    __shared__ float w2s[32];
    const int n0 = blockIdx.x * 32;
    const int s0 = blockIdx.y * 64;
    const int t  = threadIdx.x;
    const int tn = (t >> 4) * 2;  // n pair
    const int ts = (t & 15) * 4;  // s quad
    const float bb2 = b2[0];

    u64 acc[2][2];
    acc[0][0] = acc[0][1] = acc[1][0] = acc[1][1] = 0ull;

    float4 areg, breg[2]; float wreg;
    {
        int nn = t >> 3, fq = t & 7;
        areg = *(const float4*)(g_P + (size_t)(n0 + nn) * HDIM + 4 * fq);
        #pragma unroll
        for (int p = 0; p < 2; p++) {
            int idx = t + p * 256;
            int ss = idx >> 3, f2 = idx & 7;
            breg[p] = *(const float4*)(g_P + (size_t)(N_SEG + s0 + ss) * HDIM + 4 * f2);
        }
        if (t < 32) wreg = W2[t];
    }

    for (int k0 = 0; k0 < HDIM; k0 += 32) {
        __syncthreads();
        {
            int nn = t >> 3, fq = t & 7;
            int col = nn ^ (4 * fq);
            As[4 * fq + 0][col] = areg.x;
            As[4 * fq + 1][col] = areg.y;
            As[4 * fq + 2][col] = areg.z;
            As[4 * fq + 3][col] = areg.w;
            #pragma unroll
            for (int p = 0; p < 2; p++) {
                int idx = t + p * 256;
                int ss = idx >> 3, f2 = idx & 7;
                int colb = ss ^ (4 * f2);
                Bs[4 * f2 + 0][colb] = (p ? breg[1].x : breg[0].x);
                Bs[4 * f2 + 1][colb] = (p ? breg[1].y : breg[0].y);
                Bs[4 * f2 + 2][colb] = (p ? breg[1].z : breg[0].z);
                Bs[4 * f2 + 3][colb] = (p ? breg[1].w : breg[0].w);
            }
            if (t < 32) w2s[t] = wreg;
        }
        __syncthreads();
        if (k0 + 32 < HDIM) {
            int nn = t >> 3, fq = t & 7;
            areg = *(const float4*)(g_P + (size_t)(n0 + nn) * HDIM + k0 + 32 + 4 * fq);
            #pragma unroll
            for (int p = 0; p < 2; p++) {
                int idx = t + p * 256;
                int ss = idx >> 3, f2 = idx & 7;
                breg[p] = *(const float4*)(g_P + (size_t)(N_SEG + s0 + ss) * HDIM + k0 + 32 + 4 * f2);
            }
            if (t < 32) wreg = W2[k0 + 32 + t];
        }
        #pragma unroll
        for (int kk = 0; kk < 32; kk++) {
            int q4 = 4 * (kk >> 2);
            float2 a01 = *(const float2*)&As[kk][tn ^ q4];
            ulonglong2 bv = *(const ulonglong2*)&Bs[kk][ts ^ q4];
            u64 wd = dup2(w2s[kk]);
            u64 ad0 = dup2(a01.x), ad1 = dup2(a01.y);
            #pragma unroll
            for (int i = 0; i < 2; i++) {
                u64 ai = i ? ad1 : ad0;
                #pragma unroll
                for (int jp = 0; jp < 2; jp++) {
                    u64 c = add2v(ai, jp ? bv.y : bv.x);
                    float lo, hi;
                    unpack2(c, lo, hi);
                    lo = fmaxf(lo, 0.0f);
                    hi = fmaxf(hi, 0.0f);
                    fma2(acc[i][jp], pack2(lo, hi), wd);
                }
            }
        }
    }

    #pragma unroll
    for (int i = 0; i < 2; i++) {
        int n = n0 + tn + i;
        #pragma unroll
        for (int jp = 0; jp < 2; jp++) {
            float L0, L1;
            unpack2(acc[i][jp], L0, L1);
            L0 += bb2; L1 += bb2;
            int sA = s0 + ts + 2 * jp;
            g_logitsT[(size_t)sA * N_SEG + n]       = L0;
            g_logitsT[(size_t)(sA + 1) * N_SEG + n] = L1;
            float ls0 = fminf(L0, 0.0f) - log1pf(expf(-fabsf(L0)));
            float ls1 = fminf(L1, 0.0f) - log1pf(expf(-fabsf(L1)));
            g_logsigT[(size_t)sA * N_SEG + n]       = ls0;
            g_logsigT[(size_t)(sA + 1) * N_SEG + n] = ls1;
        }
    }
}

// ============================================================
// K3: serial DP (warp 0) + chunk prefetch (warps 1..3) + walk + outputs
// ============================================================
template<bool CLAMP>
__device__ __forceinline__ void dp_chunk(const float* __restrict__ buf, int c, int L,
                                         float& p0, float& p1, float& p2, float& p3,
                                         unsigned* __restrict__ rowbits)
{
    unsigned a0 = 0, a1 = 0, a2 = 0, a3 = 0;
    const int n0 = 4 * L;
    #pragma unroll 8
    for (int i = 31; i >= 0; i--) {
        float4 ls = *(const float4*)(buf + i * 128 + n0);
        float nxt3 = __shfl_down_sync(0xffffffffu, p0, 1);
        if (L == 31) nxt3 = 0.0f;               // n=127: adds 0
        float c0 = ls.x + p1;
        float c1 = ls.y + p2;
        float c2 = ls.z + p3;
        float c3 = ls.w + nxt3;
        a0 = a0 + a0 + (unsigned)(c0 >= p0);
        a1 = a1 + a1 + (unsigned)(c1 >= p1);
        a2 = a2 + a2 + (unsigned)(c2 >= p2);
        a3 = a3 + a3 + (unsigned)(c3 >= p3);
        float v0 = fmaxf(c0, p0);
        float v1 = fmaxf(c1, p1);
        float v2 = fmaxf(c2, p2);
        float v3 = fmaxf(c3, p3);
        if (CLAMP) {
            int s = c * 32 + i;
            v0 = (s >= n0     && s <= 1920 + n0) ? v0 : NEGV;
            v1 = (s >= n0 + 1 && s <= 1921 + n0) ? v1 : NEGV;
            v2 = (s >= n0 + 2 && s <= 1922 + n0) ? v2 : NEGV;
            v3 = (s >= n0 + 3 && s <= 1923 + n0) ? v3 : NEGV;
        }
        p0 = v0; p1 = v1; p2 = v2; p3 = v3;
    }
    *(uint4*)(rowbits + c * 128 + n0) = make_uint4(a0, a1, a2, a3);
}

__global__ __launch_bounds__(128) void dp_k3(float* __restrict__ out, int out_size)
{
    extern __shared__ unsigned char smraw[];
    float*    lsbuf    = (float*)smraw;                     // [2][32][128]
    unsigned* rowbits  = (unsigned*)(lsbuf + 2 * 32 * 128); // [64][128]
    int*      alignArr = (int*)(rowbits + 64 * 128);        // [128]
    float*    redbuf   = (float*)(alignArr + 128);          // [4]

    const int t = threadIdx.x;
    const int L = t & 31;
    alignArr[t] = 0;

    if (t >= 32) {
        int lt = t - 32;
        const float4* src = (const float4*)(g_logsigT + 63 * 4096);
        float4* dst = (float4*)(lsbuf + (63 & 1) * 4096);
        for (int i = lt; i < 1024; i += 96) dst[i] = src[i];
    }
    __syncthreads();

    float p0 = NEGV, p1 = NEGV, p2 = NEGV, p3 = NEGV;
    for (int c = 63; c >= 0; c--) {
        if (t >= 32) {
            if (c > 0) {
                int lt = t - 32;
                const float4* src = (const float4*)(g_logsigT + (size_t)(c - 1) * 4096);
                float4* dst = (float4*)(lsbuf + ((c - 1) & 1) * 4096);
                for (int i = lt; i < 1024; i += 96) dst[i] = src[i];
            }
        } else {
            const float* buf = lsbuf + (c & 1) * 4096;
            if (c >= 4 && c <= 59) dp_chunk<false>(buf, c, L, p0, p1, p2, p3, rowbits);
            else                   dp_chunk<true >(buf, c, L, p0, p1, p2, p3, rowbits);
        }
        __syncthreads();
    }

    if (t == 0) {
        int scur = 0;
        for (int n = 0; n < 128; n++) {
            int w = scur >> 5;
            unsigned word = rowbits[w * 128 + n] & (0xFFFFFFFFu << (scur & 31));
            while (word == 0) {
                w++;
                if (w >= 64) break;
                word = rowbits[w * 128 + n];
            }
            if (w >= 64) break;
            int s = w * 32 + (__ffs(word) - 1);
            alignArr[n] = s;
            scur = s + 1;
            if (scur >= S_VID) break;
        }
    }
    __syncthreads();

    int a = alignArr[t];
    out[(size_t)(S_VID + t) * RTOT + a] = 1.0f;
    float v = g_logitsT[(size_t)a * N_SEG + t];
    #pragma unroll
    for (int o = 16; o; o >>= 1) v += __shfl_down_sync(0xffffffffu, v, o);
    if (L == 0) redbuf[t >> 5] = v;
    __syncthreads();
    if (t == 0) {
        float sum = redbuf[0] + redbuf[1] + redbuf[2] + redbuf[3];
        if (out_size > RTOT * RTOT) out[(size_t)RTOT * RTOT] = sum * (1.0f / 128.0f);
    }
}

// ============================================================
extern "C" void kernel_launch(void* const* d_in, const int* in_sizes, int n_in,
                              void* d_out, int out_size)
{
    const float* seg = (const float*)d_in[0];
    const float* vid = (const float*)d_in[1];
    const float* W1  = (const float*)d_in[2];
    const float* b1  = (const float*)d_in[3];
    const float* W2  = (const float*)d_in[4];
    const float* b2  = (const float*)d_in[5];
    float* out = (float*)d_out;

    cudaMemsetAsync(out, 0, (size_t)out_size * sizeof(float), 0);
    gemm_k1<<<dim3(34, 4), 256>>>(seg, vid, W1, b1);
    fused_k2<<<dim3(4, 32), 256>>>(W2, b2);

    const int smem_k3 = (2 * 32 * 128) * 4 + (64 * 128) * 4 + 128 * 4 + 4 * 4;
    cudaFuncSetAttribute(dp_k3, cudaFuncAttributeMaxDynamicSharedMemorySize, smem_k3);
    dp_k3<<<1, 128, smem_k3>>>(out, out_size);
}

// round 3
// speedup vs baseline: 1.2386x; 1.1953x over previous
#include <cuda_runtime.h>
#include <stdint.h>

#define N_SEG 128
#define S_VID 2048
#define HDIM  256
#define DDIM  512
#define RTOT  (N_SEG + S_VID)   // 2176
#define NEGV  (-1000.0f)

// -------- device scratch (no allocations allowed) --------
__device__ float g_P[RTOT * HDIM];          // rows 0..127: A(+b1), rows 128..: B
__device__ float g_logitsT[S_VID * N_SEG];  // [s][n]
__device__ float g_logsigT[S_VID * N_SEG];  // [s][n]

typedef unsigned long long u64;

__device__ __forceinline__ u64 dup2(float a) {
    u64 d; asm("mov.b64 %0,{%1,%1};" : "=l"(d) : "f"(a)); return d;
}
__device__ __forceinline__ void unpack2(u64 v, float& lo, float& hi) {
    asm("mov.b64 {%0,%1},%2;" : "=f"(lo), "=f"(hi) : "l"(v));
}
__device__ __forceinline__ void fma2(u64& acc, u64 a, u64 b) {
    asm("fma.rn.f32x2 %0,%1,%2,%0;" : "+l"(acc) : "l"(a), "l"(b));
}

// ============================================================
// K1: P[r][h] = dot(x_r, W1_half_row_h) (+ b1[h] for seg rows)
//   64 rows x 64 h, BK=32, 512 threads, 2x4 microtile, f32x2 FMA
// ============================================================
__global__ __launch_bounds__(512) void gemm_k1(
    const float* __restrict__ seg, const float* __restrict__ vid,
    const float* __restrict__ W1, const float* __restrict__ b1)
{
    __shared__ float Xs[32][68];
    __shared__ float Ws[32][68];
    const int r0 = blockIdx.x * 64;
    const int h0 = blockIdx.y * 64;
    const int t  = threadIdx.x;
    const int tm = (t >> 4) * 2;   // 0..62 rows
    const int tn = (t & 15) * 4;   // 0..60 h
    const int koff = (r0 < N_SEG) ? 0 : DDIM;
    const float* xbase = (r0 < N_SEG) ? (seg + (size_t)r0 * DDIM)
                                      : (vid + (size_t)(r0 - N_SEG) * DDIM);
    const int rr = t >> 3, fq = t & 7;  // global-load mapping (1 float4/thread)

    u64 acc[2][2];
    acc[0][0] = acc[0][1] = acc[1][0] = acc[1][1] = 0ull;

    float4 xreg, wreg;
    xreg = *(const float4*)(xbase + (size_t)rr * DDIM + 4 * fq);
    wreg = *(const float4*)(W1 + (size_t)(h0 + rr) * (2 * DDIM) + koff + 4 * fq);

    for (int k0 = 0; k0 < DDIM; k0 += 32) {
        __syncthreads();
        {
            int col = rr ^ (4 * fq);
            Xs[4 * fq + 0][col] = xreg.x;
            Xs[4 * fq + 1][col] = xreg.y;
            Xs[4 * fq + 2][col] = xreg.z;
            Xs[4 * fq + 3][col] = xreg.w;
            Ws[4 * fq + 0][col] = wreg.x;
            Ws[4 * fq + 1][col] = wreg.y;
            Ws[4 * fq + 2][col] = wreg.z;
            Ws[4 * fq + 3][col] = wreg.w;
        }
        __syncthreads();
        if (k0 + 32 < DDIM) {
            xreg = *(const float4*)(xbase + (size_t)rr * DDIM + k0 + 32 + 4 * fq);
            wreg = *(const float4*)(W1 + (size_t)(h0 + rr) * (2 * DDIM) + koff + k0 + 32 + 4 * fq);
        }
        #pragma unroll
        for (int kk = 0; kk < 32; kk++) {
            int q4 = 4 * (kk >> 2);
            float2 av = *(const float2*)&Xs[kk][tm ^ q4];
            ulonglong2 wv = *(const ulonglong2*)&Ws[kk][tn ^ q4];
            u64 a0 = dup2(av.x), a1 = dup2(av.y);
            fma2(acc[0][0], a0, wv.x); fma2(acc[0][1], a0, wv.y);
            fma2(acc[1][0], a1, wv.x); fma2(acc[1][1], a1, wv.y);
        }
    }

    #pragma unroll
    for (int i = 0; i < 2; i++) {
        int r = r0 + tm + i;
        #pragma unroll
        for (int jp = 0; jp < 2; jp++) {
            float v0, v1;
            unpack2(acc[i][jp], v0, v1);
            int h = h0 + tn + 2 * jp;
            if (r0 < N_SEG) { v0 += b1[h]; v1 += b1[h + 1]; }
            *(float2*)&g_P[(size_t)r * HDIM + h] = make_float2(v0, v1);
        }
    }
}

// ============================================================
// K2: logitsT[s][n] = sum_h relu(A'[n][h] + B[s][h]) * W2[h] + b2
//     logsigT = log_sigmoid(logits)
//   64 n x 32 s tile, BK=32, 512 threads, 2n x 2s microtile (scalar math,
//   lanes span n -> coalesced float2 stores)
// ============================================================
__global__ __launch_bounds__(512) void fused_k2(
    const float* __restrict__ W2, const float* __restrict__ b2)
{
    __shared__ float As[32][68];   // 64 n, k-major swizzled
    __shared__ float Bs[32][36];   // 32 s
    __shared__ float w2s[32];
    const int n0 = blockIdx.x * 64;   // grid.x = 2
    const int s0 = blockIdx.y * 32;   // grid.y = 64
    const int t  = threadIdx.x;
    const int tn = (t & 31) * 2;      // 0..62 (lanes span n)
    const int ts = (t >> 5) * 2;      // 0..30
    const int rr = t >> 3, fq = t & 7;
    const float bb2 = b2[0];

    float acc00 = 0.f, acc01 = 0.f, acc10 = 0.f, acc11 = 0.f;

    float4 areg, breg; float wreg = 0.f;
    areg = *(const float4*)(g_P + (size_t)(n0 + rr) * HDIM + 4 * fq);
    if (t < 256) breg = *(const float4*)(g_P + (size_t)(N_SEG + s0 + rr) * HDIM + 4 * fq);
    if (t < 32)  wreg = W2[t];

    for (int k0 = 0; k0 < HDIM; k0 += 32) {
        __syncthreads();
        {
            int col = rr ^ (4 * fq);
            As[4 * fq + 0][col] = areg.x;
            As[4 * fq + 1][col] = areg.y;
            As[4 * fq + 2][col] = areg.z;
            As[4 * fq + 3][col] = areg.w;
            if (t < 256) {
                Bs[4 * fq + 0][col] = breg.x;
                Bs[4 * fq + 1][col] = breg.y;
                Bs[4 * fq + 2][col] = breg.z;
                Bs[4 * fq + 3][col] = breg.w;
            }
            if (t < 32) w2s[t] = wreg;
        }
        __syncthreads();
        if (k0 + 32 < HDIM) {
            areg = *(const float4*)(g_P + (size_t)(n0 + rr) * HDIM + k0 + 32 + 4 * fq);
            if (t < 256) breg = *(const float4*)(g_P + (size_t)(N_SEG + s0 + rr) * HDIM + k0 + 32 + 4 * fq);
            if (t < 32)  wreg = W2[k0 + 32 + t];
        }
        #pragma unroll
        for (int kk = 0; kk < 32; kk++) {
            int q4 = 4 * (kk >> 2);
            float2 an = *(const float2*)&As[kk][tn ^ q4];
            float2 bv = *(const float2*)&Bs[kk][ts ^ q4];
            float w = w2s[kk];
            acc00 += fmaxf(an.x + bv.x, 0.0f) * w;
            acc01 += fmaxf(an.x + bv.y, 0.0f) * w;
            acc10 += fmaxf(an.y + bv.x, 0.0f) * w;
            acc11 += fmaxf(an.y + bv.y, 0.0f) * w;
        }
    }

    float L[2][2] = {{acc00 + bb2, acc01 + bb2}, {acc10 + bb2, acc11 + bb2}};
    #pragma unroll
    for (int j = 0; j < 2; j++) {
        int s = s0 + ts + j;
        float L0 = L[0][j], L1 = L[1][j];
        *(float2*)&g_logitsT[(size_t)s * N_SEG + n0 + tn] = make_float2(L0, L1);
        float ls0 = fminf(L0, 0.0f) - __logf(1.0f + __expf(-fabsf(L0)));
        float ls1 = fminf(L1, 0.0f) - __logf(1.0f + __expf(-fabsf(L1)));
        *(float2*)&g_logsigT[(size_t)s * N_SEG + n0 + tn] = make_float2(ls0, ls1);
    }
}

// ============================================================
// K3: serial DP (warp 0) + batched chunk prefetch (warps 1..3) + walk
// ============================================================
template<bool CLAMP>
__device__ __forceinline__ void dp_chunk(const float* __restrict__ buf, int c, int L,
                                         float& p0, float& p1, float& p2, float& p3,
                                         unsigned* __restrict__ rowbits)
{
    unsigned a0 = 0, a1 = 0, a2 = 0, a3 = 0;
    const int n0 = 4 * L;
    #pragma unroll 8
    for (int i = 31; i >= 0; i--) {
        float4 ls = *(const float4*)(buf + i * 128 + n0);
        float nxt3 = __shfl_down_sync(0xffffffffu, p0, 1);
        if (L == 31) nxt3 = 0.0f;               // n=127: adds 0
        float c0 = ls.x + p1;
        float c1 = ls.y + p2;
        float c2 = ls.z + p3;
        float c3 = ls.w + nxt3;
        a0 = a0 + a0 + (unsigned)(c0 >= p0);
        a1 = a1 + a1 + (unsigned)(c1 >= p1);
        a2 = a2 + a2 + (unsigned)(c2 >= p2);
        a3 = a3 + a3 + (unsigned)(c3 >= p3);
        float v0 = fmaxf(c0, p0);
        float v1 = fmaxf(c1, p1);
        float v2 = fmaxf(c2, p2);
        float v3 = fmaxf(c3, p3);
        if (CLAMP) {
            int s = c * 32 + i;
            v0 = (s >= n0     && s <= 1920 + n0) ? v0 : NEGV;
            v1 = (s >= n0 + 1 && s <= 1921 + n0) ? v1 : NEGV;
            v2 = (s >= n0 + 2 && s <= 1922 + n0) ? v2 : NEGV;
            v3 = (s >= n0 + 3 && s <= 1923 + n0) ? v3 : NEGV;
        }
        p0 = v0; p1 = v1; p2 = v2; p3 = v3;
    }
    *(uint4*)(rowbits + c * 128 + n0) = make_uint4(a0, a1, a2, a3);
}

// batched chunk copy: 96 lanes, 1024 float4s, fully unrolled -> MLP 11
__device__ __forceinline__ void load_chunk(const float4* __restrict__ src,
                                           float4* __restrict__ dst, int lt)
{
    #pragma unroll
    for (int j = 0; j < 11; j++) {
        int i = lt + 96 * j;
        if (i < 1024) dst[i] = src[i];
    }
}

__global__ __launch_bounds__(128) void dp_k3(float* __restrict__ out, int out_size)
{
    extern __shared__ unsigned char smraw[];
    float*    lsbuf    = (float*)smraw;                     // [2][32][128]
    unsigned* rowbits  = (unsigned*)(lsbuf + 2 * 32 * 128); // [64][128]
    int*      alignArr = (int*)(rowbits + 64 * 128);        // [128]
    float*    redbuf   = (float*)(alignArr + 128);          // [4]

    const int t = threadIdx.x;
    const int L = t & 31;
    alignArr[t] = 0;

    if (t >= 32) {
        load_chunk((const float4*)(g_logsigT + 63 * 4096),
                   (float4*)(lsbuf + (63 & 1) * 4096), t - 32);
    }
    __syncthreads();

    float p0 = NEGV, p1 = NEGV, p2 = NEGV, p3 = NEGV;
    for (int c = 63; c >= 0; c--) {
        if (t >= 32) {
            if (c > 0) {
                load_chunk((const float4*)(g_logsigT + (size_t)(c - 1) * 4096),
                           (float4*)(lsbuf + ((c - 1) & 1) * 4096), t - 32);
            }
        } else {
            const float* buf = lsbuf + (c & 1) * 4096;
            if (c >= 4 && c <= 59) dp_chunk<false>(buf, c, L, p0, p1, p2, p3, rowbits);
            else                   dp_chunk<true >(buf, c, L, p0, p1, p2, p3, rowbits);
        }
        __syncthreads();
    }

    if (t == 0) {
        int scur = 0;
        for (int n = 0; n < 128; n++) {
            int w = scur >> 5;
            unsigned word = rowbits[w * 128 + n] & (0xFFFFFFFFu << (scur & 31));
            while (word == 0) {
                w++;
                if (w >= 64) break;
                word = rowbits[w * 128 + n];
            }
            if (w >= 64) break;
            int s = w * 32 + (__ffs(word) - 1);
            alignArr[n] = s;
            scur = s + 1;
            if (scur >= S_VID) break;
        }
    }
    __syncthreads();

    int a = alignArr[t];
    out[(size_t)(S_VID + t) * RTOT + a] = 1.0f;
    float v = g_logitsT[(size_t)a * N_SEG + t];
    #pragma unroll
    for (int o = 16; o; o >>= 1) v += __shfl_down_sync(0xffffffffu, v, o);
    if (L == 0) redbuf[t >> 5] = v;
    __syncthreads();
    if (t == 0) {
        float sum = redbuf[0] + redbuf[1] + redbuf[2] + redbuf[3];
        if (out_size > RTOT * RTOT) out[(size_t)RTOT * RTOT] = sum * (1.0f / 128.0f);
    }
}

// ============================================================
extern "C" void kernel_launch(void* const* d_in, const int* in_sizes, int n_in,
                              void* d_out, int out_size)
{
    const float* seg = (const float*)d_in[0];
    const float* vid = (const float*)d_in[1];
    const float* W1  = (const float*)d_in[2];
    const float* b1  = (const float*)d_in[3];
    const float* W2  = (const float*)d_in[4];
    const float* b2  = (const float*)d_in[5];
    float* out = (float*)d_out;

    cudaMemsetAsync(out, 0, (size_t)out_size * sizeof(float), 0);
    gemm_k1<<<dim3(34, 4), 512>>>(seg, vid, W1, b1);
    fused_k2<<<dim3(2, 64), 512>>>(W2, b2);

    const int smem_k3 = (2 * 32 * 128) * 4 + (64 * 128) * 4 + 128 * 4 + 4 * 4;
    cudaFuncSetAttribute(dp_k3, cudaFuncAttributeMaxDynamicSharedMemorySize, smem_k3);
    dp_k3<<<1, 128, smem_k3>>>(out, out_size);
}